// round 12
// baseline (speedup 1.0000x reference)
#include <cuda_runtime.h>
#include <cstdint>
#include <math_constants.h>

#define BATCH 16
#define CDIM  2048
#define TDIM  8192
#define KEEP  64

// ---- decomposition (R8-proven coarse units; 3 blocks/SM for MLP) ----
constexpr int NTHR        = 512;                 // 16 warps
constexpr int GRID        = 456;                 // 3 blocks/SM on 152 SMs
constexpr int LANES       = 64;                  // float4 t-lanes per c-partition
constexpr int CPARTS      = 8;
constexpr int CSEG        = CDIM / CPARTS;       // 256
constexpr int UNITS_PER_B = TDIM / (LANES * 4);  // 32 (256 t per unit)
constexpr int ATTN_UNITS  = BATCH * UNITS_PER_B; // 512
constexpr int SEG         = TDIM / NTHR;         // 16 values/thread in topk

// Scratch (__device__ globals; zero-init, reset by last exiting block)
__device__ float    g_attn[BATCH * TDIM];
__device__ int      g_idx [BATCH * KEEP];
__device__ float    g_val [BATCH * KEEP];
__device__ unsigned g_qa;                        // attn unit queue
__device__ unsigned g_gq[BATCH];                 // per-batch gather queues
__device__ unsigned g_bc[BATCH];                 // attn units done per batch
__device__ unsigned g_ready[BATCH];              // topk published
__device__ unsigned g_done;

__device__ __forceinline__ unsigned atomAddAcqRel(unsigned* p, unsigned v) {
    unsigned old;
    asm volatile("atom.add.acq_rel.gpu.u32 %0, [%1], %2;"
                 : "=r"(old) : "l"(p), "r"(v) : "memory");
    return old;
}
__device__ __forceinline__ unsigned ldAcquire(const unsigned* p) {
    unsigned v;
    asm volatile("ld.acquire.gpu.u32 %0, [%1];" : "=r"(v) : "l"(p) : "memory");
    return v;
}
__device__ __forceinline__ void stRelease(unsigned* p, unsigned v) {
    asm volatile("st.release.gpu.u32 [%0], %1;" :: "l"(p), "r"(v) : "memory");
}

__global__ __launch_bounds__(NTHR, 3)
void fused_kernel(const float* __restrict__ x,
                  const float* __restrict__ w,
                  const float* __restrict__ bias,
                  float* __restrict__ out,
                  int write_indices)
{
    __shared__ float ws[CDIM];                       // 8 KB, loaded once
    __shared__ union {
        float4 red[(CPARTS - 1) * LANES];            // 7 KB (attn reduce)
        float  sv[TDIM];                             // 32 KB (topk)
    } sm;
    __shared__ float    lmax[NTHR];
    __shared__ int      lidx[NTHR];
    __shared__ float    wmax[NTHR / 32];
    __shared__ int      widxs[NTHR / 32];
    __shared__ int      s_sel, s_flag;
    __shared__ int      s_type, s_a, s_b, s_t;
    __shared__ float    s_scale;

    const int tid  = threadIdx.x;
    const int wid  = tid >> 5;
    const int lane = tid & 31;
    const float bb = bias[0];

    for (int i = tid; i < CDIM; i += NTHR) ws[i] = w[i];

    // tid0-resident scheduler state (gather-first: prompt dispatch + backfill)
    int      lowb = 0;
    unsigned fullmask = 0;
    int      attn_left = 1;

    for (;;) {
        __syncthreads();   // close previous unit before tid0 writes shared
        if (tid == 0) {
            int type = -1, pa = 0, pb = 0;
            // 1) gather from lowest ready batch with capacity
            for (int b = lowb; b < BATCH; ++b) {
                if ((fullmask >> b) & 1u) { if (b == lowb) ++lowb; continue; }
                if (ldAcquire(&g_ready[b]) == 0u) break;
                const unsigned k = atomicAdd(&g_gq[b], 1u);
                if (k < KEEP) { type = 1; pa = b; pb = (int)k; break; }
                fullmask |= 1u << b; if (b == lowb) ++lowb;
            }
            // 2) attn
            if (type < 0 && attn_left) {
                const unsigned u = atomicAdd(&g_qa, 1u);
                if (u < ATTN_UNITS) { type = 0; pa = (int)u; }
                else attn_left = 0;
            }
            // 3) drain
            if (type < 0) type = (lowb >= BATCH) ? 2 : 3;

            if (type == 1) {
                const int   t = g_idx[pa * KEEP + pb];
                const float v = g_val[pa * KEEP + pb];
                s_t = t; s_scale = v + (1.0f - v);   // match reference rounding
            }
            s_type = type; s_a = pa; s_b = pb;
        }
        __syncthreads();
        const int type = s_type;
        if (type == 2) break;
        if (type == 3) { if (tid == 0) __nanosleep(400); continue; }

        if (type == 0) {
            // ============ attn unit: (b, tch) -> 256 t, full c ============
            const int u   = s_a;
            const int b   = u >> 5;                 // b-major
            const int tch = u & (UNITS_PER_B - 1);

            const int l64 = tid & (LANES - 1);
            const int cp  = tid / LANES;            // 0..7
            const int t4  = tch * LANES + l64;      // global float4 t index

            const float4* __restrict__ x4 =
                reinterpret_cast<const float4*>(x) + (size_t)b * CDIM * (TDIM / 4);

            float4 acc = make_float4(0.f, 0.f, 0.f, 0.f);
            const int cbeg = cp * CSEG;
            #pragma unroll 8
            for (int c = cbeg; c < cbeg + CSEG; ++c) {
                const float  wv = ws[c];
                const float4 xv = x4[(size_t)c * (TDIM / 4) + t4];
                acc.x = fmaf(xv.x, wv, acc.x);
                acc.y = fmaf(xv.y, wv, acc.y);
                acc.z = fmaf(xv.z, wv, acc.z);
                acc.w = fmaf(xv.w, wv, acc.w);
            }

            if (cp > 0) sm.red[(cp - 1) * LANES + l64] = acc;
            __syncthreads();

            if (cp == 0) {
                #pragma unroll
                for (int p = 0; p < CPARTS - 1; ++p) {
                    const float4 q = sm.red[p * LANES + l64];
                    acc.x += q.x; acc.y += q.y; acc.z += q.z; acc.w += q.w;
                }
                float4 o = make_float4(acc.x + bb, acc.y + bb, acc.z + bb, acc.w + bb);
                reinterpret_cast<float4*>(g_attn)[(size_t)b * (TDIM / 4) + t4] = o;
            }
            __syncthreads();

            if (tid == 0) {
                const unsigned old = atomAddAcqRel(&g_bc[b], 1u);
                s_flag = (old == UNITS_PER_B - 1);
            }
            __syncthreads();
            if (!s_flag) continue;

            // ============ top-64 for batch b ============
            {
                const float* __restrict__ a = g_attn + (size_t)b * TDIM;
                for (int i = tid; i < TDIM; i += NTHR) sm.sv[i] = __ldcg(&a[i]);
            }
            __syncthreads();

            const int base = tid * SEG;
            {
                float bm = -CUDART_INF_F; int bi = 0;
                #pragma unroll
                for (int i = 0; i < SEG; ++i) {
                    const float v = sm.sv[base + i];
                    if (v > bm) { bm = v; bi = base + i; }  // strict > -> lowest idx
                }
                lmax[tid] = bm; lidx[tid] = bi;
            }
            __syncthreads();

            for (int k = 0; k < KEEP; ++k) {
                float v  = lmax[tid];
                int   id = lidx[tid];
                #pragma unroll
                for (int off = 16; off; off >>= 1) {
                    const float ov = __shfl_down_sync(0xffffffffu, v, off);
                    const int   oi = __shfl_down_sync(0xffffffffu, id, off);
                    if (ov > v || (ov == v && oi < id)) { v = ov; id = oi; }
                }
                if (lane == 0) { wmax[wid] = v; widxs[wid] = id; }
                __syncthreads();

                if (tid == 0) {
                    float bv = wmax[0]; int bI = widxs[0];
                    #pragma unroll
                    for (int g = 1; g < NTHR / 32; ++g) {
                        const float ov = wmax[g]; const int oi = widxs[g];
                        if (ov > bv || (ov == bv && oi < bI)) { bv = ov; bI = oi; }
                    }
                    g_idx[b * KEEP + k] = bI;
                    g_val[b * KEEP + k] = bv;
                    s_sel = bI;
                    sm.sv[bI] = -CUDART_INF_F;
                }
                __syncthreads();

                const int sel = s_sel;
                if ((sel / SEG) == tid) {
                    float bm = -CUDART_INF_F; int bi = 0;
                    #pragma unroll
                    for (int i = 0; i < SEG; ++i) {
                        const float vv = sm.sv[base + i];
                        if (vv > bm) { bm = vv; bi = base + i; }
                    }
                    lmax[tid] = bm; lidx[tid] = bi;
                }
                __syncthreads();
            }
            if (tid == 0) stRelease(&g_ready[b], 1u);   // publish g_idx/g_val
        } else {
            // ============ gather unit: (s_a=b, s_b=k) ============
            const int gb = s_a, gk = s_b;
            const int t  = s_t;
            const float scale = s_scale;

            const float* __restrict__ xp = x + (size_t)gb * CDIM * TDIM + t;
            float* __restrict__ op = out + ((size_t)gb * KEEP + gk) * CDIM;

            float r[CDIM / NTHR];
            #pragma unroll
            for (int j = 0; j < CDIM / NTHR; ++j)
                r[j] = xp[(size_t)(tid + j * NTHR) * TDIM];
            #pragma unroll
            for (int j = 0; j < CDIM / NTHR; ++j)
                op[tid + j * NTHR] = r[j] * scale;

            if (write_indices && tid == 0)
                out[(size_t)BATCH * KEEP * CDIM + gb * KEEP + gk] = (float)t;
        }
    }

    // last exiting block resets control state for the next graph replay
    if (tid == 0) {
        const unsigned d = atomicAdd(&g_done, 1u);
        if (d == GRID - 1) {
            g_qa = 0; g_done = 0;
            #pragma unroll
            for (int i = 0; i < BATCH; ++i) { g_gq[i] = 0; g_bc[i] = 0; g_ready[i] = 0; }
            __threadfence();
        }
    }
}

extern "C" void kernel_launch(void* const* d_in, const int* in_sizes, int n_in,
                              void* d_out, int out_size)
{
    const float* x    = (const float*)d_in[0];
    const float* w    = (const float*)d_in[1];
    const float* bias = (const float*)d_in[2];
    float* out = (float*)d_out;

    const int lat_elems = BATCH * KEEP * CDIM;   // 2,097,152
    const int widx = (out_size >= lat_elems + BATCH * KEEP) ? 1 : 0;

    fused_kernel<<<GRID, NTHR>>>(x, w, bias, out, widx);
}

// round 13
// speedup vs baseline: 1.2666x; 1.2666x over previous
#include <cuda_runtime.h>
#include <cstdint>
#include <math_constants.h>

#define BATCH 16
#define CDIM  2048
#define TDIM  8192
#define KEEP  64

// ---- decomposition (R8-proven coarse units) ----
constexpr int NTHR        = 512;                 // 16 warps
constexpr int GRID        = 304;                 // 2 blocks/SM on 152 SMs
constexpr int LANES       = 64;                  // float4 t-lanes per c-partition
constexpr int CPARTS      = 8;
constexpr int CSEG        = CDIM / CPARTS;       // 256
constexpr int UNITS_PER_B = TDIM / (LANES * 4);  // 32 (256 t per unit)
constexpr int ATTN_UNITS  = BATCH * UNITS_PER_B; // 512
constexpr int SEG         = TDIM / NTHR;         // 16 values/thread in topk

// Scratch (__device__ globals; zero-init, reset by last exiting block)
__device__ float    g_attn[BATCH * TDIM];
__device__ int      g_idx [BATCH * KEEP];
__device__ float    g_val [BATCH * KEEP];
__device__ unsigned g_qa;                        // attn unit queue
__device__ unsigned g_gq[BATCH];                 // per-batch gather queues
__device__ unsigned g_bc[BATCH];                 // attn units done per batch
__device__ unsigned g_ready[BATCH];              // topk published
__device__ unsigned g_done;

__device__ __forceinline__ unsigned atomAddAcqRel(unsigned* p, unsigned v) {
    unsigned old;
    asm volatile("atom.add.acq_rel.gpu.u32 %0, [%1], %2;"
                 : "=r"(old) : "l"(p), "r"(v) : "memory");
    return old;
}
__device__ __forceinline__ unsigned ldAcquire(const unsigned* p) {
    unsigned v;
    asm volatile("ld.acquire.gpu.u32 %0, [%1];" : "=r"(v) : "l"(p) : "memory");
    return v;
}
__device__ __forceinline__ void stRelease(unsigned* p, unsigned v) {
    asm volatile("st.release.gpu.u32 [%0], %1;" :: "l"(p), "r"(v) : "memory");
}
// Volatile / no-allocate global read: bypasses L1/L2 allocation; candidate for
// sector-granularity (32B) DRAM fetch instead of 128B line fill.
__device__ __forceinline__ float ldg_cv(const float* p) {
    float v;
    asm volatile("ld.global.cv.f32 %0, [%1];" : "=f"(v) : "l"(p) : "memory");
    return v;
}

__global__ __launch_bounds__(NTHR, 2)
void fused_kernel(const float* __restrict__ x,
                  const float* __restrict__ w,
                  const float* __restrict__ bias,
                  float* __restrict__ out,
                  int write_indices)
{
    __shared__ float ws[CDIM];                       // 8 KB, loaded once
    __shared__ union {
        float4 red[(CPARTS - 1) * LANES];            // 7 KB (attn reduce)
        float  sv[TDIM];                             // 32 KB (topk)
    } sm;
    __shared__ float    lmax[NTHR];
    __shared__ int      lidx[NTHR];
    __shared__ float    wmax[NTHR / 32];
    __shared__ int      widxs[NTHR / 32];
    __shared__ int      s_sel, s_flag;
    __shared__ int      s_type, s_a, s_b, s_t;
    __shared__ float    s_scale;

    const int tid  = threadIdx.x;
    const int wid  = tid >> 5;
    const int lane = tid & 31;
    const float bb = bias[0];

    for (int i = tid; i < CDIM; i += NTHR) ws[i] = w[i];

    // tid0-resident scheduler state (gather-first: prompt dispatch)
    int      lowb = 0;
    unsigned fullmask = 0;
    int      attn_left = 1;

    for (;;) {
        __syncthreads();   // close previous unit before tid0 writes shared
        if (tid == 0) {
            int type = -1, pa = 0, pb = 0;
            // 1) gather from lowest ready batch with capacity
            for (int b = lowb; b < BATCH; ++b) {
                if ((fullmask >> b) & 1u) { if (b == lowb) ++lowb; continue; }
                if (ldAcquire(&g_ready[b]) == 0u) break;
                const unsigned k = atomicAdd(&g_gq[b], 1u);
                if (k < KEEP) { type = 1; pa = b; pb = (int)k; break; }
                fullmask |= 1u << b; if (b == lowb) ++lowb;
            }
            // 2) attn
            if (type < 0 && attn_left) {
                const unsigned u = atomicAdd(&g_qa, 1u);
                if (u < ATTN_UNITS) { type = 0; pa = (int)u; }
                else attn_left = 0;
            }
            // 3) drain
            if (type < 0) type = (lowb >= BATCH) ? 2 : 3;

            if (type == 1) {
                const int   t = g_idx[pa * KEEP + pb];
                const float v = g_val[pa * KEEP + pb];
                s_t = t; s_scale = v + (1.0f - v);   // match reference rounding
            }
            s_type = type; s_a = pa; s_b = pb;
        }
        __syncthreads();
        const int type = s_type;
        if (type == 2) break;
        if (type == 3) { if (tid == 0) __nanosleep(400); continue; }

        if (type == 0) {
            // ============ attn unit: (b, tch) -> 256 t, full c ============
            const int u   = s_a;
            const int b   = u >> 5;                 // b-major
            const int tch = u & (UNITS_PER_B - 1);

            const int l64 = tid & (LANES - 1);
            const int cp  = tid / LANES;            // 0..7
            const int t4  = tch * LANES + l64;      // global float4 t index

            const float4* __restrict__ x4 =
                reinterpret_cast<const float4*>(x) + (size_t)b * CDIM * (TDIM / 4);

            float4 acc = make_float4(0.f, 0.f, 0.f, 0.f);
            const int cbeg = cp * CSEG;
            #pragma unroll 8
            for (int c = cbeg; c < cbeg + CSEG; ++c) {
                const float  wv = ws[c];
                const float4 xv = x4[(size_t)c * (TDIM / 4) + t4];
                acc.x = fmaf(xv.x, wv, acc.x);
                acc.y = fmaf(xv.y, wv, acc.y);
                acc.z = fmaf(xv.z, wv, acc.z);
                acc.w = fmaf(xv.w, wv, acc.w);
            }

            if (cp > 0) sm.red[(cp - 1) * LANES + l64] = acc;
            __syncthreads();

            if (cp == 0) {
                #pragma unroll
                for (int p = 0; p < CPARTS - 1; ++p) {
                    const float4 q = sm.red[p * LANES + l64];
                    acc.x += q.x; acc.y += q.y; acc.z += q.z; acc.w += q.w;
                }
                float4 o = make_float4(acc.x + bb, acc.y + bb, acc.z + bb, acc.w + bb);
                reinterpret_cast<float4*>(g_attn)[(size_t)b * (TDIM / 4) + t4] = o;
            }
            __syncthreads();

            if (tid == 0) {
                const unsigned old = atomAddAcqRel(&g_bc[b], 1u);
                s_flag = (old == UNITS_PER_B - 1);
            }
            __syncthreads();
            if (!s_flag) continue;

            // ============ top-64 for batch b ============
            {
                const float* __restrict__ a = g_attn + (size_t)b * TDIM;
                for (int i = tid; i < TDIM; i += NTHR) sm.sv[i] = __ldcg(&a[i]);
            }
            __syncthreads();

            const int base = tid * SEG;
            {
                float bm = -CUDART_INF_F; int bi = 0;
                #pragma unroll
                for (int i = 0; i < SEG; ++i) {
                    const float v = sm.sv[base + i];
                    if (v > bm) { bm = v; bi = base + i; }  // strict > -> lowest idx
                }
                lmax[tid] = bm; lidx[tid] = bi;
            }
            __syncthreads();

            for (int k = 0; k < KEEP; ++k) {
                float v  = lmax[tid];
                int   id = lidx[tid];
                #pragma unroll
                for (int off = 16; off; off >>= 1) {
                    const float ov = __shfl_down_sync(0xffffffffu, v, off);
                    const int   oi = __shfl_down_sync(0xffffffffu, id, off);
                    if (ov > v || (ov == v && oi < id)) { v = ov; id = oi; }
                }
                if (lane == 0) { wmax[wid] = v; widxs[wid] = id; }
                __syncthreads();

                if (tid == 0) {
                    float bv = wmax[0]; int bI = widxs[0];
                    #pragma unroll
                    for (int g = 1; g < NTHR / 32; ++g) {
                        const float ov = wmax[g]; const int oi = widxs[g];
                        if (ov > bv || (ov == bv && oi < bI)) { bv = ov; bI = oi; }
                    }
                    g_idx[b * KEEP + k] = bI;
                    g_val[b * KEEP + k] = bv;
                    s_sel = bI;
                    sm.sv[bI] = -CUDART_INF_F;
                }
                __syncthreads();

                const int sel = s_sel;
                if ((sel / SEG) == tid) {
                    float bm = -CUDART_INF_F; int bi = 0;
                    #pragma unroll
                    for (int i = 0; i < SEG; ++i) {
                        const float vv = sm.sv[base + i];
                        if (vv > bm) { bm = vv; bi = base + i; }
                    }
                    lmax[tid] = bm; lidx[tid] = bi;
                }
                __syncthreads();
            }
            if (tid == 0) stRelease(&g_ready[b], 1u);   // publish g_idx/g_val
        } else {
            // ============ gather unit: (s_a=b, s_b=k) — .cv no-allocate reads ============
            const int gb = s_a, gk = s_b;
            const int t  = s_t;
            const float scale = s_scale;

            const float* __restrict__ xp = x + (size_t)gb * CDIM * TDIM + t;
            float* __restrict__ op = out + ((size_t)gb * KEEP + gk) * CDIM;

            float r[CDIM / NTHR];
            #pragma unroll
            for (int j = 0; j < CDIM / NTHR; ++j)
                r[j] = ldg_cv(xp + (size_t)(tid + j * NTHR) * TDIM);
            #pragma unroll
            for (int j = 0; j < CDIM / NTHR; ++j)
                op[tid + j * NTHR] = r[j] * scale;

            if (write_indices && tid == 0)
                out[(size_t)BATCH * KEEP * CDIM + gb * KEEP + gk] = (float)t;
        }
    }

    // last exiting block resets control state for the next graph replay
    if (tid == 0) {
        const unsigned d = atomicAdd(&g_done, 1u);
        if (d == GRID - 1) {
            g_qa = 0; g_done = 0;
            #pragma unroll
            for (int i = 0; i < BATCH; ++i) { g_gq[i] = 0; g_bc[i] = 0; g_ready[i] = 0; }
            __threadfence();
        }
    }
}

extern "C" void kernel_launch(void* const* d_in, const int* in_sizes, int n_in,
                              void* d_out, int out_size)
{
    const float* x    = (const float*)d_in[0];
    const float* w    = (const float*)d_in[1];
    const float* bias = (const float*)d_in[2];
    float* out = (float*)d_out;

    const int lat_elems = BATCH * KEEP * CDIM;   // 2,097,152
    const int widx = (out_size >= lat_elems + BATCH * KEEP) ? 1 : 0;

    fused_kernel<<<GRID, NTHR>>>(x, w, bias, out, widx);
}

// round 14
// speedup vs baseline: 1.2901x; 1.0186x over previous
#include <cuda_runtime.h>
#include <cstdint>
#include <math_constants.h>

#define BATCH 16
#define CDIM  2048
#define TDIM  8192
#define KEEP  64

// ---- decomposition (R8-proven coarse units) ----
constexpr int NTHR        = 512;                 // 16 warps
constexpr int GRID        = 304;                 // 2 blocks/SM on 152 SMs
constexpr int LANES       = 64;                  // float4 t-lanes per c-partition
constexpr int CPARTS      = 8;
constexpr int CSEG        = CDIM / CPARTS;       // 256
constexpr int UNITS_PER_B = TDIM / (LANES * 4);  // 32 (256 t per unit)
constexpr int ATTN_UNITS  = BATCH * UNITS_PER_B; // 512
constexpr int WSEG        = TDIM / 16;           // 512 values per warp (topk)
constexpr int LSEG        = WSEG / 32;           // 16 values per lane

// Scratch (__device__ globals; zero-init, reset by last exiting block)
__device__ float    g_attn[BATCH * TDIM];
__device__ int      g_idx [BATCH * KEEP];
__device__ float    g_val [BATCH * KEEP];
__device__ unsigned g_qa;                        // attn unit queue
__device__ unsigned g_gq[BATCH];                 // per-batch gather queues
__device__ unsigned g_bc[BATCH];                 // attn units done per batch
__device__ unsigned g_ready[BATCH];              // topk published
__device__ unsigned g_done;

__device__ __forceinline__ unsigned atomAddAcqRel(unsigned* p, unsigned v) {
    unsigned old;
    asm volatile("atom.add.acq_rel.gpu.u32 %0, [%1], %2;"
                 : "=r"(old) : "l"(p), "r"(v) : "memory");
    return old;
}
__device__ __forceinline__ unsigned ldAcquire(const unsigned* p) {
    unsigned v;
    asm volatile("ld.acquire.gpu.u32 %0, [%1];" : "=r"(v) : "l"(p) : "memory");
    return v;
}
__device__ __forceinline__ void stRelease(unsigned* p, unsigned v) {
    asm volatile("st.release.gpu.u32 [%0], %1;" :: "l"(p), "r"(v) : "memory");
}

__global__ __launch_bounds__(NTHR, 2)
void fused_kernel(const float* __restrict__ x,
                  const float* __restrict__ w,
                  const float* __restrict__ bias,
                  float* __restrict__ out,
                  int write_indices)
{
    __shared__ float ws[CDIM];                       // 8 KB, loaded once
    __shared__ union {
        float4 red[(CPARTS - 1) * LANES];            // 7 KB (attn reduce)
        float  sv[TDIM];                             // 32 KB (topk working copy)
    } sm;
    __shared__ float    wlv[16 * KEEP];              // 4 KB: per-warp sorted top-64 vals
    __shared__ int      wli[16 * KEEP];              // 4 KB: per-warp sorted top-64 idxs
    __shared__ int      s_type, s_a, s_b, s_t, s_flag;
    __shared__ float    s_scale;

    const int tid  = threadIdx.x;
    const int wid  = tid >> 5;
    const int lane = tid & 31;
    const float bb = bias[0];

    for (int i = tid; i < CDIM; i += NTHR) ws[i] = w[i];

    // tid0-resident scheduler state (gather-first: prompt dispatch)
    int      lowb = 0;
    unsigned fullmask = 0;
    int      attn_left = 1;

    for (;;) {
        __syncthreads();   // close previous unit before tid0 writes shared
        if (tid == 0) {
            int type = -1, pa = 0, pb = 0;
            // 1) gather from lowest ready batch with capacity
            for (int b = lowb; b < BATCH; ++b) {
                if ((fullmask >> b) & 1u) { if (b == lowb) ++lowb; continue; }
                if (ldAcquire(&g_ready[b]) == 0u) break;
                const unsigned k = atomicAdd(&g_gq[b], 1u);
                if (k < KEEP) { type = 1; pa = b; pb = (int)k; break; }
                fullmask |= 1u << b; if (b == lowb) ++lowb;
            }
            // 2) attn
            if (type < 0 && attn_left) {
                const unsigned u = atomicAdd(&g_qa, 1u);
                if (u < ATTN_UNITS) { type = 0; pa = (int)u; }
                else attn_left = 0;
            }
            // 3) drain
            if (type < 0) type = (lowb >= BATCH) ? 2 : 3;

            if (type == 1) {
                const int   t = g_idx[pa * KEEP + pb];
                const float v = g_val[pa * KEEP + pb];
                s_t = t; s_scale = v + (1.0f - v);   // match reference rounding
            }
            s_type = type; s_a = pa; s_b = pb;
        }
        __syncthreads();
        const int type = s_type;
        if (type == 2) break;
        if (type == 3) { if (tid == 0) __nanosleep(400); continue; }

        if (type == 0) {
            // ============ attn unit: (b, tch) -> 256 t, full c ============
            const int u   = s_a;
            const int b   = u >> 5;                 // b-major
            const int tch = u & (UNITS_PER_B - 1);

            const int l64 = tid & (LANES - 1);
            const int cp  = tid / LANES;            // 0..7
            const int t4  = tch * LANES + l64;      // global float4 t index

            const float4* __restrict__ x4 =
                reinterpret_cast<const float4*>(x) + (size_t)b * CDIM * (TDIM / 4);

            float4 acc = make_float4(0.f, 0.f, 0.f, 0.f);
            const int cbeg = cp * CSEG;
            #pragma unroll 8
            for (int c = cbeg; c < cbeg + CSEG; ++c) {
                const float  wv = ws[c];
                const float4 xv = x4[(size_t)c * (TDIM / 4) + t4];
                acc.x = fmaf(xv.x, wv, acc.x);
                acc.y = fmaf(xv.y, wv, acc.y);
                acc.z = fmaf(xv.z, wv, acc.z);
                acc.w = fmaf(xv.w, wv, acc.w);
            }

            if (cp > 0) sm.red[(cp - 1) * LANES + l64] = acc;
            __syncthreads();

            if (cp == 0) {
                #pragma unroll
                for (int p = 0; p < CPARTS - 1; ++p) {
                    const float4 q = sm.red[p * LANES + l64];
                    acc.x += q.x; acc.y += q.y; acc.z += q.z; acc.w += q.w;
                }
                float4 o = make_float4(acc.x + bb, acc.y + bb, acc.z + bb, acc.w + bb);
                reinterpret_cast<float4*>(g_attn)[(size_t)b * (TDIM / 4) + t4] = o;
            }
            __syncthreads();

            if (tid == 0) {
                const unsigned old = atomAddAcqRel(&g_bc[b], 1u);
                s_flag = (old == UNITS_PER_B - 1);
            }
            __syncthreads();
            if (!s_flag) continue;

            // ============ top-64 for batch b: warp-parallel extract + merge ============
            {
                const float* __restrict__ a = g_attn + (size_t)b * TDIM;
                for (int i = tid; i < TDIM; i += NTHR) sm.sv[i] = __ldcg(&a[i]);
            }
            __syncthreads();

            // Phase A: each warp extracts sorted top-64 of its 512-value segment.
            // No block barriers; ties -> lowest index (strict > on scan, oi<id on reduce).
            {
                const int base = wid * WSEG + lane * LSEG;  // lane's 16 contiguous values
                float bm = -CUDART_INF_F; int bi = base;
                #pragma unroll
                for (int i = 0; i < LSEG; ++i) {
                    const float v = sm.sv[base + i];
                    if (v > bm) { bm = v; bi = base + i; }
                }
                for (int k = 0; k < KEEP; ++k) {
                    float v = bm; int id = bi;
                    #pragma unroll
                    for (int off = 16; off; off >>= 1) {     // butterfly: all lanes get winner
                        const float ov = __shfl_xor_sync(0xffffffffu, v, off);
                        const int   oi = __shfl_xor_sync(0xffffffffu, id, off);
                        if (ov > v || (ov == v && oi < id)) { v = ov; id = oi; }
                    }
                    if (lane == 0) { wlv[wid * KEEP + k] = v; wli[wid * KEEP + k] = id; }
                    // owner lane removes winner and rescans its 16
                    if ((id >> 4) == (wid << 5) + lane) {    // id/16 == global lane slot
                        sm.sv[id] = -CUDART_INF_F;
                        float nm = -CUDART_INF_F; int ni = base;
                        #pragma unroll
                        for (int i = 0; i < LSEG; ++i) {
                            const float vv = sm.sv[base + i];
                            if (vv > nm) { nm = vv; ni = base + i; }
                        }
                        bm = nm; bi = ni;
                    }
                }
            }
            __syncthreads();

            // Phase B: warp 0 merges 16 sorted lists (ties -> lowest warp = lowest index).
            if (wid == 0) {
                int   ptr = 0;
                float v  = (lane < 16) ? wlv[lane * KEEP] : -CUDART_INF_F;
                int   id = (lane < 16) ? wli[lane * KEEP] : 0x7fffffff;
                for (int k = 0; k < KEEP; ++k) {
                    float m = v; int mi = id; int mw = lane;
                    #pragma unroll
                    for (int off = 16; off; off >>= 1) {
                        const float ov = __shfl_xor_sync(0xffffffffu, m, off);
                        const int   oi = __shfl_xor_sync(0xffffffffu, mi, off);
                        const int   ow = __shfl_xor_sync(0xffffffffu, mw, off);
                        if (ov > m || (ov == m && ow < mw)) { m = ov; mi = oi; mw = ow; }
                    }
                    if (lane == 0) {
                        g_idx[b * KEEP + k] = mi;
                        g_val[b * KEEP + k] = m;
                    }
                    if (lane == mw) {           // winner's list advances
                        ++ptr;
                        if (ptr < KEEP) { v = wlv[lane * KEEP + ptr]; id = wli[lane * KEEP + ptr]; }
                        else            { v = -CUDART_INF_F;          id = 0x7fffffff; }
                    }
                }
                if (lane == 0) stRelease(&g_ready[b], 1u);   // publish g_idx/g_val
            }
        } else {
            // ============ gather unit: (s_a=b, s_b=k) ============
            const int gb = s_a, gk = s_b;
            const int t  = s_t;
            const float scale = s_scale;

            const float* __restrict__ xp = x + (size_t)gb * CDIM * TDIM + t;
            float* __restrict__ op = out + ((size_t)gb * KEEP + gk) * CDIM;

            float r[CDIM / NTHR];
            #pragma unroll
            for (int j = 0; j < CDIM / NTHR; ++j)
                r[j] = xp[(size_t)(tid + j * NTHR) * TDIM];
            #pragma unroll
            for (int j = 0; j < CDIM / NTHR; ++j)
                op[tid + j * NTHR] = r[j] * scale;

            if (write_indices && tid == 0)
                out[(size_t)BATCH * KEEP * CDIM + gb * KEEP + gk] = (float)t;
        }
    }

    // last exiting block resets control state for the next graph replay
    if (tid == 0) {
        const unsigned d = atomicAdd(&g_done, 1u);
        if (d == GRID - 1) {
            g_qa = 0; g_done = 0;
            #pragma unroll
            for (int i = 0; i < BATCH; ++i) { g_gq[i] = 0; g_bc[i] = 0; g_ready[i] = 0; }
            __threadfence();
        }
    }
}

extern "C" void kernel_launch(void* const* d_in, const int* in_sizes, int n_in,
                              void* d_out, int out_size)
{
    const float* x    = (const float*)d_in[0];
    const float* w    = (const float*)d_in[1];
    const float* bias = (const float*)d_in[2];
    float* out = (float*)d_out;

    const int lat_elems = BATCH * KEEP * CDIM;   // 2,097,152
    const int widx = (out_size >= lat_elems + BATCH * KEEP) ? 1 : 0;

    fused_kernel<<<GRID, NTHR>>>(x, w, bias, out, widx);
}